// round 3
// baseline (speedup 1.0000x reference)
#include <cuda_runtime.h>
#include <cuda_fp16.h>
#include <stdint.h>

#define B_    8
#define NV_   128
#define NQ_   512
#define DIN   128
#define DPROJ 512
#define HD    256

// smem strides (element units): row step = 4 banks -> conflict-free frag loads
#define PR_S  136   // proj tiles [x][136] f16
#define VW_S  264   // score vw/q tiles [x][264] f16 (K=256)
#define SC_S  132   // score matrix [j][132] fp32 (i=128)
#define EB_S  136   // exp tile [j][136] f16
#define VT_S  136   // vT tile [d][136] f16

// ---- device scratch (allocations forbidden) ----
__device__ __half g_q16 [B_*NQ_*DPROJ];   // q_  : [b*512+j][512]
__device__ __half g_vw16[B_*NV_*DPROJ];   // v_*wa : [b*128+i][512]
__device__ __half g_vT16[B_*DPROJ*NV_];   // v_^T : [b][512][128]
__device__ float  g_head[B_*DPROJ];

__device__ __forceinline__ void mma16816(float* c, const uint32_t* a, const uint32_t* b) {
    asm volatile(
        "mma.sync.aligned.m16n8k16.row.col.f32.f16.f16.f32 "
        "{%0,%1,%2,%3}, {%4,%5,%6,%7}, {%8,%9}, {%0,%1,%2,%3};\n"
        : "+f"(c[0]), "+f"(c[1]), "+f"(c[2]), "+f"(c[3])
        : "r"(a[0]), "r"(a[1]), "r"(a[2]), "r"(a[3]), "r"(b[0]), "r"(b[1]));
}

// ============================================================
// Combined projection kernel. grid (4 nTiles, 40 mTiles), 512 thr.
//   by < 8  : v-proj tile (also emits vw = v*wa and vT transposed)
//   by >= 8 : q-proj tile
// W converted fp32->f16 + transposed in-kernel (L2 resident).
// First 4 CTAs also zero g_head.
// ============================================================
__global__ __launch_bounds__(512) void proj_k(
    const float* __restrict__ v, const float* __restrict__ q,
    const float* __restrict__ Wv, const float* __restrict__ Wq,
    const float* __restrict__ bv, const float* __restrict__ bq,
    const float* __restrict__ wa)
{
    extern __shared__ __align__(16) char smem[];
    __half* As = (__half*)smem;                 // [128][136]
    __half* Bs = (__half*)(smem + 128*PR_S*2);  // [128][136] (W^T tile)

    int t = threadIdx.x;
    int by = blockIdx.y;
    bool isV = by < 8;
    int my = isV ? by : (by - 8);
    int bn = blockIdx.x * 128;
    int bm = my * 128;

    if (by == 0) {   // zero head accumulator (score_k runs strictly after)
        g_head[blockIdx.x*1024 + t] = 0.f;
        g_head[blockIdx.x*1024 + 512 + t] = 0.f;
    }

    const float* A    = isV ? v  : q;
    const float* W    = isV ? Wv : Wq;
    const float* bias = isV ? bv : bq;

    // load A fp32 -> f16 smem [m][k]
    #pragma unroll
    for (int it = 0; it < 8; it++) {
        int fi = t + it*512;                 // 4096 float4
        int m = fi >> 5, k = (fi & 31)*4;
        float4 f = *(const float4*)(A + (size_t)(bm+m)*DIN + k);
        __half2 h0 = __floats2half2_rn(f.x, f.y);
        __half2 h1 = __floats2half2_rn(f.z, f.w);
        uint2 u; u.x = *(uint32_t*)&h0; u.y = *(uint32_t*)&h1;
        *(uint2*)(As + m*PR_S + k) = u;
    }
    // load W fp32 [k][n] -> Bs f16 [n][k] (transpose + convert)
    #pragma unroll
    for (int it = 0; it < 8; it++) {
        int fi = t + it*512;                 // 4096 float4
        int k = fi >> 5, n4 = (fi & 31)*4;
        float4 w = *(const float4*)(W + (size_t)k*DPROJ + bn + n4);
        Bs[(n4+0)*PR_S + k] = __float2half(w.x);
        Bs[(n4+1)*PR_S + k] = __float2half(w.y);
        Bs[(n4+2)*PR_S + k] = __float2half(w.z);
        Bs[(n4+3)*PR_S + k] = __float2half(w.w);
    }
    __syncthreads();

    int lane = t & 31, wid = t >> 5;
    int warpM = wid >> 2, warpN = wid & 3;   // 4x4 warps, 32x32 warp tile
    int lr = lane >> 2, lc = (lane & 3)*2;

    float acc[2][4][4] = {};
    #pragma unroll
    for (int ks = 0; ks < 8; ks++) {
        int k0 = ks*16;
        uint32_t a[2][4], b[4][2];
        #pragma unroll
        for (int mt = 0; mt < 2; mt++) {
            const __half* ab = As + (warpM*32 + mt*16 + lr)*PR_S + k0 + lc;
            a[mt][0] = *(const uint32_t*)ab;
            a[mt][1] = *(const uint32_t*)(ab + 8*PR_S);
            a[mt][2] = *(const uint32_t*)(ab + 8);
            a[mt][3] = *(const uint32_t*)(ab + 8*PR_S + 8);
        }
        #pragma unroll
        for (int nt = 0; nt < 4; nt++) {
            const __half* bb = Bs + (warpN*32 + nt*8 + lr)*PR_S + k0 + lc;
            b[nt][0] = *(const uint32_t*)bb;
            b[nt][1] = *(const uint32_t*)(bb + 8);
        }
        #pragma unroll
        for (int mt = 0; mt < 2; mt++)
            #pragma unroll
            for (int nt = 0; nt < 4; nt++)
                mma16816(acc[mt][nt], a[mt], b[nt]);
    }

    if (isV) __syncthreads();   // As reused as transpose staging

    #pragma unroll
    for (int mt = 0; mt < 2; mt++) {
        int rowL = warpM*32 + mt*16 + lr;
        #pragma unroll
        for (int nt = 0; nt < 4; nt++) {
            int colL = warpN*32 + nt*8 + lc;
            int col = bn + colL;
            float b0 = bias[col], b1 = bias[col+1];
            float v00 = acc[mt][nt][0] + b0, v01 = acc[mt][nt][1] + b1;
            float v10 = acc[mt][nt][2] + b0, v11 = acc[mt][nt][3] + b1;
            if (!isV) {
                int row = bm + rowL;
                *(__half2*)(g_q16 + (size_t)row*DPROJ + col) =
                    __floats2half2_rn(v00, v01);
                *(__half2*)(g_q16 + (size_t)(row+8)*DPROJ + col) =
                    __floats2half2_rn(v10, v11);
            } else {
                int row = bm + rowL;
                float w0 = wa[col & 255], w1 = wa[(col+1) & 255];
                *(__half2*)(g_vw16 + (size_t)row*DPROJ + col) =
                    __floats2half2_rn(v00*w0, v01*w1);
                *(__half2*)(g_vw16 + (size_t)(row+8)*DPROJ + col) =
                    __floats2half2_rn(v10*w0, v11*w1);
                __half* tr = As;   // tr[n][m]
                tr[colL*PR_S + rowL]       = __float2half(v00);
                tr[(colL+1)*PR_S + rowL]   = __float2half(v01);
                tr[colL*PR_S + rowL+8]     = __float2half(v10);
                tr[(colL+1)*PR_S + rowL+8] = __float2half(v11);
            }
        }
    }

    if (isV) {
        __syncthreads();
        const __half* tr = As;
        int b = my;   // one M tile == one batch for v
        #pragma unroll
        for (int it = 0; it < 4; it++) {
            int fi = t + it*512;             // 2048 float4
            int n = fi >> 4, k = (fi & 15)*8;
            *(float4*)(g_vT16 + ((size_t)b*DPROJ + bn + n)*NV_ + k) =
                *(const float4*)(tr + n*PR_S + k);
        }
    }
}

// ============================================================
// Score kernel: per (jt, h, b). 512 threads.
//  P1: S[128i,64j] = vw @ q^T (mma) -> softmax over i -> att write
//  P2: T[64j,256d] = e @ vT^T (mma) -> head atomics weighted by inv*q
// ============================================================
__global__ __launch_bounds__(512) void score_k(float* __restrict__ att_out)
{
    extern __shared__ __align__(16) char smem[];
    __half* vws = (__half*)smem;                  // P1 vw [128][264]; P2 vT [256][136]
    __half* qs  = (__half*)(smem + 69632);        // [64][264]
    float*  sc  = (float*) (smem + 103424);       // [64][132]
    __half* ebf = (__half*)(smem + 137216);       // [64][136]
    float*  inv = (float*) (smem + 154624);       // [64]

    int t = threadIdx.x;
    int jt = blockIdx.x, h = blockIdx.y, b = blockIdx.z;
    int lane = t & 31, wid = t >> 5;
    int lr = lane >> 2, lc = (lane & 3)*2;

    const __half* vwg = g_vw16 + ((size_t)b*NV_)*DPROJ + h*HD;
    const __half* qg  = g_q16  + ((size_t)(b*NQ_ + jt*64))*DPROJ + h*HD;

    #pragma unroll
    for (int it = 0; it < 8; it++) {
        int fi = t + it*512;                 // 4096 float4 : vw 128x256
        int i = fi >> 5, k = (fi & 31)*8;
        *(float4*)(vws + i*VW_S + k) = *(const float4*)(vwg + (size_t)i*DPROJ + k);
    }
    #pragma unroll
    for (int it = 0; it < 4; it++) {
        int fi = t + it*512;                 // 2048 float4 : q 64x256
        int j = fi >> 5, k = (fi & 31)*8;
        *(float4*)(qs + j*VW_S + k) = *(const float4*)(qg + (size_t)j*DPROJ + k);
    }
    __syncthreads();

    // -------- phase 1: warps 4(i) x 4(j), warp tile 32x16 --------
    {
        int iw = (wid >> 2)*32, jw = (wid & 3)*16;
        float acc[2][2][4] = {};
        #pragma unroll
        for (int ks = 0; ks < 16; ks++) {
            int k0 = ks*16;
            uint32_t a[2][4], bq[2][2];
            #pragma unroll
            for (int mi = 0; mi < 2; mi++) {
                const __half* ab = vws + (iw + mi*16 + lr)*VW_S + k0 + lc;
                a[mi][0] = *(const uint32_t*)ab;
                a[mi][1] = *(const uint32_t*)(ab + 8*VW_S);
                a[mi][2] = *(const uint32_t*)(ab + 8);
                a[mi][3] = *(const uint32_t*)(ab + 8*VW_S + 8);
            }
            #pragma unroll
            for (int nj = 0; nj < 2; nj++) {
                const __half* bb = qs + (jw + nj*8 + lr)*VW_S + k0 + lc;
                bq[nj][0] = *(const uint32_t*)bb;
                bq[nj][1] = *(const uint32_t*)(bb + 8);
            }
            #pragma unroll
            for (int mi = 0; mi < 2; mi++)
                #pragma unroll
                for (int nj = 0; nj < 2; nj++)
                    mma16816(acc[mi][nj], a[mi], bq[nj]);
        }
        #pragma unroll
        for (int mi = 0; mi < 2; mi++) {
            int i0 = iw + mi*16 + lr;
            #pragma unroll
            for (int nj = 0; nj < 2; nj++) {
                int j0 = jw + nj*8 + lc;
                sc[j0*SC_S + i0]       = acc[mi][nj][0];
                sc[(j0+1)*SC_S + i0]   = acc[mi][nj][1];
                sc[j0*SC_S + i0+8]     = acc[mi][nj][2];
                sc[(j0+1)*SC_S + i0+8] = acc[mi][nj][3];
            }
        }
    }
    __syncthreads();

    // -------- softmax over i : 16 warps x 4 cols --------
    #pragma unroll
    for (int rr = 0; rr < 4; rr++) {
        int j = wid*4 + rr;
        float4 x = *(float4*)(sc + j*SC_S + lane*4);
        float mx = fmaxf(fmaxf(x.x, x.y), fmaxf(x.z, x.w));
        #pragma unroll
        for (int off = 16; off; off >>= 1)
            mx = fmaxf(mx, __shfl_xor_sync(0xffffffffu, mx, off));
        float4 e;
        e.x = __expf(x.x - mx); e.y = __expf(x.y - mx);
        e.z = __expf(x.z - mx); e.w = __expf(x.w - mx);
        float s = e.x + e.y + e.z + e.w;
        #pragma unroll
        for (int off = 16; off; off >>= 1)
            s += __shfl_xor_sync(0xffffffffu, s, off);
        *(float4*)(sc + j*SC_S + lane*4) = e;
        *(__half2*)(ebf + j*EB_S + lane*4)     = __floats2half2_rn(e.x, e.y);
        *(__half2*)(ebf + j*EB_S + lane*4 + 2) = __floats2half2_rn(e.z, e.w);
        if (lane == 0) inv[j] = 1.0f / s;
    }
    __syncthreads();

    // -------- load vT (overwrites vws) + write att --------
    const __half* vtg = g_vT16 + ((size_t)b*DPROJ + h*HD)*NV_;
    #pragma unroll
    for (int it = 0; it < 8; it++) {
        int fi = t + it*512;                 // 4096 float4 : vT 256x128
        int d = fi >> 4, k = (fi & 15)*8;
        *(float4*)(vws + d*VT_S + k) = *(const float4*)(vtg + (size_t)d*NV_ + k);
    }
    float* attp = att_out + ((size_t)(b*2 + h)*NV_)*NQ_ + jt*64;
    #pragma unroll
    for (int it = 0; it < 16; it++) {
        int e = it*512 + t;
        int i = e >> 6, j = e & 63;
        attp[(size_t)i*NQ_ + j] = sc[j*SC_S + i] * inv[j];
    }
    __syncthreads();

    // -------- phase 2: warps 2(j) x 8(d), warp tile 32x32 --------
    {
        int jw2 = (wid >> 3)*32, dw = (wid & 7)*32;
        float acc[2][4][4] = {};
        #pragma unroll
        for (int ks = 0; ks < 8; ks++) {
            int k0 = ks*16;
            uint32_t a[2][4], bv[4][2];
            #pragma unroll
            for (int mi = 0; mi < 2; mi++) {
                const __half* ab = ebf + (jw2 + mi*16 + lr)*EB_S + k0 + lc;
                a[mi][0] = *(const uint32_t*)ab;
                a[mi][1] = *(const uint32_t*)(ab + 8*EB_S);
                a[mi][2] = *(const uint32_t*)(ab + 8);
                a[mi][3] = *(const uint32_t*)(ab + 8*EB_S + 8);
            }
            #pragma unroll
            for (int nt = 0; nt < 4; nt++) {
                const __half* bb = vws + (dw + nt*8 + lr)*VT_S + k0 + lc;
                bv[nt][0] = *(const uint32_t*)bb;
                bv[nt][1] = *(const uint32_t*)(bb + 8);
            }
            #pragma unroll
            for (int mi = 0; mi < 2; mi++)
                #pragma unroll
                for (int nt = 0; nt < 4; nt++)
                    mma16816(acc[mi][nt], a[mi], bv[nt]);
        }
        float* headp = g_head + (b*2 + h)*HD;
        #pragma unroll
        for (int nt = 0; nt < 4; nt++) {
            int d0 = dw + nt*8 + lc;
            float va = 0.f, vb = 0.f;
            #pragma unroll
            for (int mi = 0; mi < 2; mi++) {
                int j0 = jw2 + mi*16 + lr, j1 = j0 + 8;
                float w0 = inv[j0], w1 = inv[j1];
                float q00 = __half2float(qs[j0*VW_S + d0]);
                float q01 = __half2float(qs[j0*VW_S + d0+1]);
                float q10 = __half2float(qs[j1*VW_S + d0]);
                float q11 = __half2float(qs[j1*VW_S + d0+1]);
                va += acc[mi][nt][0]*w0*q00 + acc[mi][nt][2]*w1*q10;
                vb += acc[mi][nt][1]*w0*q01 + acc[mi][nt][3]*w1*q11;
            }
            va += __shfl_xor_sync(0xffffffffu, va, 4);
            va += __shfl_xor_sync(0xffffffffu, va, 8);
            va += __shfl_xor_sync(0xffffffffu, va, 16);
            vb += __shfl_xor_sync(0xffffffffu, vb, 4);
            vb += __shfl_xor_sync(0xffffffffu, vb, 8);
            vb += __shfl_xor_sync(0xffffffffu, vb, 16);
            if (lr == 0) {
                atomicAdd(headp + d0,     va);
                atomicAdd(headp + d0 + 1, vb);
            }
        }
    }
}

// ============================================================
// fused = head(8x512) @ Wo(512x256) + bo
// ============================================================
__global__ __launch_bounds__(256) void fused_k(
    const float* __restrict__ Wo, const float* __restrict__ bo,
    float* __restrict__ out)
{
    __shared__ float hs[512];
    __shared__ float part[8][32];
    int dt = blockIdx.x, b = blockIdx.y;
    int tid = threadIdx.x;
    hs[tid]       = g_head[b*DPROJ + tid];
    hs[tid + 256] = g_head[b*DPROJ + 256 + tid];
    __syncthreads();
    int kg = tid >> 5, dl = tid & 31;
    int dcol = dt*32 + dl;
    float acc = 0.f;
    #pragma unroll 8
    for (int k = kg*64; k < kg*64 + 64; k++)
        acc += hs[k] * Wo[(size_t)k*HD + dcol];
    part[kg][dl] = acc;
    __syncthreads();
    if (tid < 32) {
        float s = 0.f;
        #pragma unroll
        for (int g = 0; g < 8; g++) s += part[g][tid];
        out[b*HD + dt*32 + tid] = s + bo[dt*32 + tid];
    }
}

// ============================================================
extern "C" void kernel_launch(void* const* d_in, const int* in_sizes, int n_in,
                              void* d_out, int out_size)
{
    const float* v  = (const float*)d_in[0];
    const float* q  = (const float*)d_in[1];
    const float* Wv = (const float*)d_in[2];
    const float* bv = (const float*)d_in[3];
    const float* Wq = (const float*)d_in[4];
    const float* bq = (const float*)d_in[5];
    const float* wa = (const float*)d_in[6];
    // d_in[7] = ba : constant shift before softmax -> drops out
    const float* Wo = (const float*)d_in[8];
    const float* bo = (const float*)d_in[9];
    float* out = (float*)d_out;

    const int PSM = 2 * 128 * PR_S * 2;   // 69632 B
    const int SSM = 154880;               // score smem
    cudaFuncSetAttribute(proj_k,  cudaFuncAttributeMaxDynamicSharedMemorySize, PSM);
    cudaFuncSetAttribute(score_k, cudaFuncAttributeMaxDynamicSharedMemorySize, SSM);

    proj_k<<<dim3(4, 40), 512, PSM>>>(v, q, Wv, Wq, bv, bq, wa);
    score_k<<<dim3(8, 2, 8), 512, SSM>>>(out + B_*HD);
    fused_k<<<dim3(8, 8), 256>>>(Wo, bo, out);
}

// round 4
// speedup vs baseline: 1.2174x; 1.2174x over previous
#include <cuda_runtime.h>
#include <cuda_fp16.h>
#include <stdint.h>

#define B_    8
#define NV_   128
#define NQ_   512
#define DIN   128
#define DPROJ 512
#define HD    256

// smem strides (element units): row step = 4 banks -> conflict-free frag loads
#define PR_S  136   // proj tiles [x][136] f16
#define VW_S  264   // score vw/q tiles [x][264] f16 (K=256)
#define SC_S  132   // score matrix [j][132] fp32 (i=128)
#define EB_S  136   // exp tile [j][136] f16
#define VT_S  136   // vT tile [d][136] f16

// ---- device scratch (allocations forbidden) ----
__device__ __half g_q16 [B_*NQ_*DPROJ];   // q_  : [b*512+j][512]
__device__ __half g_vw16[B_*NV_*DPROJ];   // v_*wa : [b*128+i][512]
__device__ __half g_vT16[B_*DPROJ*NV_];   // v_^T : [b][512][128]
__device__ __half g_WvT [DPROJ*DIN];      // Wv^T f16 [512][128]
__device__ __half g_WqT [DPROJ*DIN];      // Wq^T f16 [512][128]
__device__ float  g_head[B_*DPROJ];

__device__ __forceinline__ void mma16816(float* c, const uint32_t* a, const uint32_t* b) {
    asm volatile(
        "mma.sync.aligned.m16n8k16.row.col.f32.f16.f16.f32 "
        "{%0,%1,%2,%3}, {%4,%5,%6,%7}, {%8,%9}, {%0,%1,%2,%3};\n"
        : "+f"(c[0]), "+f"(c[1]), "+f"(c[2]), "+f"(c[3])
        : "r"(a[0]), "r"(a[1]), "r"(a[2]), "r"(a[3]), "r"(b[0]), "r"(b[1]));
}

// ============================================================
// One-shot: W[128][512] fp32 -> WT[512][128] f16 (both), + zero g_head.
// grid (256, 2), 256 thr. Coalesced read; scattered f16 write (small, once).
// ============================================================
__global__ void transposeW_k(const float* __restrict__ Wv, const float* __restrict__ Wq)
{
    const float* W = blockIdx.y ? Wq : Wv;
    __half* WT = blockIdx.y ? g_WqT : g_WvT;
    int idx = blockIdx.x*256 + threadIdx.x;   // 0..65535
    float val = W[idx];
    int k = idx >> 9, n = idx & 511;
    WT[n*DIN + k] = __float2half(val);
    if (blockIdx.y == 0 && idx < B_*DPROJ) g_head[idx] = 0.f;
}

// ============================================================
// Combined projection. grid (4 nTiles, 40 mTiles), 512 thr.
//   by < 8 : v tile (emits vw = v_*wa and vT)   by >= 8 : q tile
// ============================================================
__global__ __launch_bounds__(512) void proj_k(
    const float* __restrict__ v, const float* __restrict__ q,
    const float* __restrict__ bv, const float* __restrict__ bq,
    const float* __restrict__ wa)
{
    extern __shared__ __align__(16) char smem[];
    __half* As = (__half*)smem;                 // [128][136]
    __half* Bs = (__half*)(smem + 128*PR_S*2);  // [128][136] (W^T tile, k-minor)

    int t = threadIdx.x;
    int by = blockIdx.y;
    bool isV = by < 8;
    int my = isV ? by : (by - 8);
    int bn = blockIdx.x * 128;
    int bm = my * 128;

    const float* A    = isV ? v  : q;
    const float* bias = isV ? bv : bq;
    const __half* WT  = isV ? g_WvT : g_WqT;

    // load A fp32 -> f16 smem [m][k]
    #pragma unroll
    for (int it = 0; it < 8; it++) {
        int fi = t + it*512;                 // 4096 float4
        int m = fi >> 5, k = (fi & 31)*4;
        float4 f = *(const float4*)(A + (size_t)(bm+m)*DIN + k);
        __half2 h0 = __floats2half2_rn(f.x, f.y);
        __half2 h1 = __floats2half2_rn(f.z, f.w);
        uint2 u; u.x = *(uint32_t*)&h0; u.y = *(uint32_t*)&h1;
        *(uint2*)(As + m*PR_S + k) = u;
    }
    // load WT f16 [n][k] via float4 (conflict-free)
    #pragma unroll
    for (int it = 0; it < 4; it++) {
        int fi = t + it*512;                 // 2048 float4
        int n = fi >> 4, k = (fi & 15)*8;
        *(float4*)(Bs + n*PR_S + k) = *(const float4*)(WT + (size_t)(bn+n)*DIN + k);
    }
    __syncthreads();

    int lane = t & 31, wid = t >> 5;
    int warpM = wid >> 2, warpN = wid & 3;   // 4x4 warps, 32x32 warp tile
    int lr = lane >> 2, lc = (lane & 3)*2;

    float acc[2][4][4] = {};
    #pragma unroll
    for (int ks = 0; ks < 8; ks++) {
        int k0 = ks*16;
        uint32_t a[2][4], b[4][2];
        #pragma unroll
        for (int mt = 0; mt < 2; mt++) {
            const __half* ab = As + (warpM*32 + mt*16 + lr)*PR_S + k0 + lc;
            a[mt][0] = *(const uint32_t*)ab;
            a[mt][1] = *(const uint32_t*)(ab + 8*PR_S);
            a[mt][2] = *(const uint32_t*)(ab + 8);
            a[mt][3] = *(const uint32_t*)(ab + 8*PR_S + 8);
        }
        #pragma unroll
        for (int nt = 0; nt < 4; nt++) {
            const __half* bb = Bs + (warpN*32 + nt*8 + lr)*PR_S + k0 + lc;
            b[nt][0] = *(const uint32_t*)bb;
            b[nt][1] = *(const uint32_t*)(bb + 8);
        }
        #pragma unroll
        for (int mt = 0; mt < 2; mt++)
            #pragma unroll
            for (int nt = 0; nt < 4; nt++)
                mma16816(acc[mt][nt], a[mt], b[nt]);
    }

    if (isV) __syncthreads();   // As reused as transpose staging

    #pragma unroll
    for (int mt = 0; mt < 2; mt++) {
        int rowL = warpM*32 + mt*16 + lr;
        #pragma unroll
        for (int nt = 0; nt < 4; nt++) {
            int colL = warpN*32 + nt*8 + lc;
            int col = bn + colL;
            float b0 = bias[col], b1 = bias[col+1];
            float v00 = acc[mt][nt][0] + b0, v01 = acc[mt][nt][1] + b1;
            float v10 = acc[mt][nt][2] + b0, v11 = acc[mt][nt][3] + b1;
            int row = bm + rowL;
            if (!isV) {
                *(__half2*)(g_q16 + (size_t)row*DPROJ + col) =
                    __floats2half2_rn(v00, v01);
                *(__half2*)(g_q16 + (size_t)(row+8)*DPROJ + col) =
                    __floats2half2_rn(v10, v11);
            } else {
                float w0 = wa[col & 255], w1 = wa[(col+1) & 255];
                *(__half2*)(g_vw16 + (size_t)row*DPROJ + col) =
                    __floats2half2_rn(v00*w0, v01*w1);
                *(__half2*)(g_vw16 + (size_t)(row+8)*DPROJ + col) =
                    __floats2half2_rn(v10*w0, v11*w1);
                __half* tr = As;   // tr[n][m]
                tr[colL*PR_S + rowL]       = __float2half(v00);
                tr[(colL+1)*PR_S + rowL]   = __float2half(v01);
                tr[colL*PR_S + rowL+8]     = __float2half(v10);
                tr[(colL+1)*PR_S + rowL+8] = __float2half(v11);
            }
        }
    }

    if (isV) {
        __syncthreads();
        const __half* tr = As;
        int b = my;   // one M tile == one batch for v
        #pragma unroll
        for (int it = 0; it < 4; it++) {
            int fi = t + it*512;             // 2048 float4
            int n = fi >> 4, k = (fi & 15)*8;
            *(float4*)(g_vT16 + ((size_t)b*DPROJ + bn + n)*NV_ + k) =
                *(const float4*)(tr + n*PR_S + k);
        }
    }
}

// ============================================================
// Score kernel: per (jt, h, b). 512 threads.
//  P1: S[128i,64j] = vw @ q^T (mma) -> softmax over i -> att write
//  P2: T[64j,256d] = e @ vT^T (mma) -> head atomics weighted by inv*q
// ============================================================
__global__ __launch_bounds__(512) void score_k(float* __restrict__ att_out)
{
    extern __shared__ __align__(16) char smem[];
    __half* vws = (__half*)smem;                  // P1 vw [128][264]; P2 vT [256][136]
    __half* qs  = (__half*)(smem + 69632);        // [64][264]
    float*  sc  = (float*) (smem + 103424);       // [64][132]
    __half* ebf = (__half*)(smem + 137216);       // [64][136]
    float*  inv = (float*) (smem + 154624);       // [64]

    int t = threadIdx.x;
    int jt = blockIdx.x, h = blockIdx.y, b = blockIdx.z;
    int lane = t & 31, wid = t >> 5;
    int lr = lane >> 2, lc = (lane & 3)*2;

    const __half* vwg = g_vw16 + ((size_t)b*NV_)*DPROJ + h*HD;
    const __half* qg  = g_q16  + ((size_t)(b*NQ_ + jt*64))*DPROJ + h*HD;

    #pragma unroll
    for (int it = 0; it < 8; it++) {
        int fi = t + it*512;                 // 4096 float4 : vw 128x256
        int i = fi >> 5, k = (fi & 31)*8;
        *(float4*)(vws + i*VW_S + k) = *(const float4*)(vwg + (size_t)i*DPROJ + k);
    }
    #pragma unroll
    for (int it = 0; it < 4; it++) {
        int fi = t + it*512;                 // 2048 float4 : q 64x256
        int j = fi >> 5, k = (fi & 31)*8;
        *(float4*)(qs + j*VW_S + k) = *(const float4*)(qg + (size_t)j*DPROJ + k);
    }
    __syncthreads();

    // -------- phase 1: warps 4(i) x 4(j), warp tile 32x16 --------
    {
        int iw = (wid >> 2)*32, jw = (wid & 3)*16;
        float acc[2][2][4] = {};
        #pragma unroll
        for (int ks = 0; ks < 16; ks++) {
            int k0 = ks*16;
            uint32_t a[2][4], bq[2][2];
            #pragma unroll
            for (int mi = 0; mi < 2; mi++) {
                const __half* ab = vws + (iw + mi*16 + lr)*VW_S + k0 + lc;
                a[mi][0] = *(const uint32_t*)ab;
                a[mi][1] = *(const uint32_t*)(ab + 8*VW_S);
                a[mi][2] = *(const uint32_t*)(ab + 8);
                a[mi][3] = *(const uint32_t*)(ab + 8*VW_S + 8);
            }
            #pragma unroll
            for (int nj = 0; nj < 2; nj++) {
                const __half* bb = qs + (jw + nj*8 + lr)*VW_S + k0 + lc;
                bq[nj][0] = *(const uint32_t*)bb;
                bq[nj][1] = *(const uint32_t*)(bb + 8);
            }
            #pragma unroll
            for (int mi = 0; mi < 2; mi++)
                #pragma unroll
                for (int nj = 0; nj < 2; nj++)
                    mma16816(acc[mi][nj], a[mi], bq[nj]);
        }
        #pragma unroll
        for (int mi = 0; mi < 2; mi++) {
            int i0 = iw + mi*16 + lr;
            #pragma unroll
            for (int nj = 0; nj < 2; nj++) {
                int j0 = jw + nj*8 + lc;
                sc[j0*SC_S + i0]       = acc[mi][nj][0];
                sc[(j0+1)*SC_S + i0]   = acc[mi][nj][1];
                sc[j0*SC_S + i0+8]     = acc[mi][nj][2];
                sc[(j0+1)*SC_S + i0+8] = acc[mi][nj][3];
            }
        }
    }
    __syncthreads();

    // -------- softmax over i : 16 warps x 4 cols --------
    #pragma unroll
    for (int rr = 0; rr < 4; rr++) {
        int j = wid*4 + rr;
        float4 x = *(float4*)(sc + j*SC_S + lane*4);
        float mx = fmaxf(fmaxf(x.x, x.y), fmaxf(x.z, x.w));
        #pragma unroll
        for (int off = 16; off; off >>= 1)
            mx = fmaxf(mx, __shfl_xor_sync(0xffffffffu, mx, off));
        float4 e;
        e.x = __expf(x.x - mx); e.y = __expf(x.y - mx);
        e.z = __expf(x.z - mx); e.w = __expf(x.w - mx);
        float s = e.x + e.y + e.z + e.w;
        #pragma unroll
        for (int off = 16; off; off >>= 1)
            s += __shfl_xor_sync(0xffffffffu, s, off);
        *(float4*)(sc + j*SC_S + lane*4) = e;
        *(__half2*)(ebf + j*EB_S + lane*4)     = __floats2half2_rn(e.x, e.y);
        *(__half2*)(ebf + j*EB_S + lane*4 + 2) = __floats2half2_rn(e.z, e.w);
        if (lane == 0) inv[j] = 1.0f / s;
    }
    __syncthreads();

    // -------- load vT (overwrites vws) + write att --------
    const __half* vtg = g_vT16 + ((size_t)b*DPROJ + h*HD)*NV_;
    #pragma unroll
    for (int it = 0; it < 8; it++) {
        int fi = t + it*512;                 // 4096 float4 : vT 256x128
        int d = fi >> 4, k = (fi & 15)*8;
        *(float4*)(vws + d*VT_S + k) = *(const float4*)(vtg + (size_t)d*NV_ + k);
    }
    float* attp = att_out + ((size_t)(b*2 + h)*NV_)*NQ_ + jt*64;
    #pragma unroll
    for (int it = 0; it < 16; it++) {
        int e = it*512 + t;
        int i = e >> 6, j = e & 63;
        attp[(size_t)i*NQ_ + j] = sc[j*SC_S + i] * inv[j];
    }
    __syncthreads();

    // -------- phase 2: warps 2(j) x 8(d), warp tile 32x32 --------
    {
        int jw2 = (wid >> 3)*32, dw = (wid & 7)*32;
        float acc[2][4][4] = {};
        #pragma unroll
        for (int ks = 0; ks < 8; ks++) {
            int k0 = ks*16;
            uint32_t a[2][4], bv[4][2];
            #pragma unroll
            for (int mi = 0; mi < 2; mi++) {
                const __half* ab = ebf + (jw2 + mi*16 + lr)*EB_S + k0 + lc;
                a[mi][0] = *(const uint32_t*)ab;
                a[mi][1] = *(const uint32_t*)(ab + 8*EB_S);
                a[mi][2] = *(const uint32_t*)(ab + 8);
                a[mi][3] = *(const uint32_t*)(ab + 8*EB_S + 8);
            }
            #pragma unroll
            for (int nt = 0; nt < 4; nt++) {
                const __half* bb = vws + (dw + nt*8 + lr)*VT_S + k0 + lc;
                bv[nt][0] = *(const uint32_t*)bb;
                bv[nt][1] = *(const uint32_t*)(bb + 8);
            }
            #pragma unroll
            for (int mi = 0; mi < 2; mi++)
                #pragma unroll
                for (int nt = 0; nt < 4; nt++)
                    mma16816(acc[mi][nt], a[mi], bv[nt]);
        }
        float* headp = g_head + (b*2 + h)*HD;
        #pragma unroll
        for (int nt = 0; nt < 4; nt++) {
            int d0 = dw + nt*8 + lc;
            float va = 0.f, vb = 0.f;
            #pragma unroll
            for (int mi = 0; mi < 2; mi++) {
                int j0 = jw2 + mi*16 + lr, j1 = j0 + 8;
                float w0 = inv[j0], w1 = inv[j1];
                float q00 = __half2float(qs[j0*VW_S + d0]);
                float q01 = __half2float(qs[j0*VW_S + d0+1]);
                float q10 = __half2float(qs[j1*VW_S + d0]);
                float q11 = __half2float(qs[j1*VW_S + d0+1]);
                va += acc[mi][nt][0]*w0*q00 + acc[mi][nt][2]*w1*q10;
                vb += acc[mi][nt][1]*w0*q01 + acc[mi][nt][3]*w1*q11;
            }
            va += __shfl_xor_sync(0xffffffffu, va, 4);
            va += __shfl_xor_sync(0xffffffffu, va, 8);
            va += __shfl_xor_sync(0xffffffffu, va, 16);
            vb += __shfl_xor_sync(0xffffffffu, vb, 4);
            vb += __shfl_xor_sync(0xffffffffu, vb, 8);
            vb += __shfl_xor_sync(0xffffffffu, vb, 16);
            if (lr == 0) {
                atomicAdd(headp + d0,     va);
                atomicAdd(headp + d0 + 1, vb);
            }
        }
    }
}

// ============================================================
// fused = head(8x512) @ Wo(512x256) + bo
// ============================================================
__global__ __launch_bounds__(256) void fused_k(
    const float* __restrict__ Wo, const float* __restrict__ bo,
    float* __restrict__ out)
{
    __shared__ float hs[512];
    __shared__ float part[8][32];
    int dt = blockIdx.x, b = blockIdx.y;
    int tid = threadIdx.x;
    hs[tid]       = g_head[b*DPROJ + tid];
    hs[tid + 256] = g_head[b*DPROJ + 256 + tid];
    __syncthreads();
    int kg = tid >> 5, dl = tid & 31;
    int dcol = dt*32 + dl;
    float acc = 0.f;
    #pragma unroll 8
    for (int k = kg*64; k < kg*64 + 64; k++)
        acc += hs[k] * Wo[(size_t)k*HD + dcol];
    part[kg][dl] = acc;
    __syncthreads();
    if (tid < 32) {
        float s = 0.f;
        #pragma unroll
        for (int g = 0; g < 8; g++) s += part[g][tid];
        out[b*HD + dt*32 + tid] = s + bo[dt*32 + tid];
    }
}

// ============================================================
extern "C" void kernel_launch(void* const* d_in, const int* in_sizes, int n_in,
                              void* d_out, int out_size)
{
    const float* v  = (const float*)d_in[0];
    const float* q  = (const float*)d_in[1];
    const float* Wv = (const float*)d_in[2];
    const float* bv = (const float*)d_in[3];
    const float* Wq = (const float*)d_in[4];
    const float* bq = (const float*)d_in[5];
    const float* wa = (const float*)d_in[6];
    // d_in[7] = ba : constant shift before softmax -> drops out
    const float* Wo = (const float*)d_in[8];
    const float* bo = (const float*)d_in[9];
    float* out = (float*)d_out;

    const int PSM = 2 * 128 * PR_S * 2;   // 69632 B
    const int SSM = 154880;               // score smem
    cudaFuncSetAttribute(proj_k,  cudaFuncAttributeMaxDynamicSharedMemorySize, PSM);
    cudaFuncSetAttribute(score_k, cudaFuncAttributeMaxDynamicSharedMemorySize, SSM);

    transposeW_k<<<dim3(256, 2), 256>>>(Wv, Wq);
    proj_k<<<dim3(4, 40), 512, PSM>>>(v, q, bv, bq, wa);
    score_k<<<dim3(8, 2, 8), 512, SSM>>>(out + B_*HD);
    fused_k<<<dim3(8, 8), 256>>>(Wo, bo, out);
}

// round 5
// speedup vs baseline: 1.2376x; 1.0166x over previous
#include <cuda_runtime.h>
#include <cuda_fp16.h>
#include <stdint.h>

#define B_    8
#define NV_   128
#define NQ_   512
#define DIN   128
#define DPROJ 512
#define HD    256

// smem strides (element units): row step = 4 banks -> conflict-free frag loads
#define PR_S  136   // proj tiles [x][136] f16
#define VW_S  264   // score vw/q tiles [x][264] f16 (K=256)
#define SC_S  132   // score matrix [j][132] fp32 (i=128)
#define EB_S  136   // exp tile [j][136] f16
#define VT_S  136   // vT tile [d][136] f16

// ---- device scratch (allocations forbidden) ----
__device__ __half g_q16 [B_*NQ_*DPROJ];   // q_  : [b*512+j][512]
__device__ __half g_vw16[B_*NV_*DPROJ];   // v_*wa : [b*128+i][512]
__device__ __half g_vT16[B_*DPROJ*NV_];   // v_^T : [b][512][128]
__device__ __half g_WvT [DPROJ*DIN];      // Wv^T f16 [512][128]
__device__ __half g_WqT [DPROJ*DIN];      // Wq^T f16 [512][128]
__device__ float  g_head[B_*DPROJ];

__device__ __forceinline__ void mma16816(float* c, const uint32_t* a, const uint32_t* b) {
    asm volatile(
        "mma.sync.aligned.m16n8k16.row.col.f32.f16.f16.f32 "
        "{%0,%1,%2,%3}, {%4,%5,%6,%7}, {%8,%9}, {%0,%1,%2,%3};\n"
        : "+f"(c[0]), "+f"(c[1]), "+f"(c[2]), "+f"(c[3])
        : "r"(a[0]), "r"(a[1]), "r"(a[2]), "r"(a[3]), "r"(b[0]), "r"(b[1]));
}

// ============================================================
// Tiled W transpose: W[128][512] fp32 -> WT[512][128] f16, via smem.
// grid (8 ntiles, 2 which), 256 thr. Coalesced read AND write.
// CTA (0,0) also zeroes g_head.
// ============================================================
__global__ __launch_bounds__(256) void transposeW_k(
    const float* __restrict__ Wv, const float* __restrict__ Wq)
{
    __shared__ __align__(16) __half s[64*136];   // [nn][k], stride 136
    const float* W = blockIdx.y ? Wq : Wv;
    __half* WT = blockIdx.y ? g_WqT : g_WvT;
    int t = threadIdx.x;
    int n0 = blockIdx.x * 64;

    if (blockIdx.x == 0 && blockIdx.y == 0) {
        #pragma unroll
        for (int it = 0; it < 16; it++) g_head[t + it*256] = 0.f;
    }

    #pragma unroll
    for (int it = 0; it < 32; it++) {
        int fi = t + it*256;                 // 8192 elements
        int k = fi >> 6, nn = fi & 63;
        s[nn*136 + k] = __float2half(W[(size_t)k*DPROJ + n0 + nn]);
    }
    __syncthreads();
    #pragma unroll
    for (int it = 0; it < 4; it++) {
        int fi = t + it*256;                 // 1024 float4
        int n = fi >> 4, kq = (fi & 15)*8;
        *(float4*)(WT + (size_t)(n0 + n)*DIN + kq) =
            *(const float4*)(s + n*136 + kq);
    }
}

// ============================================================
// Combined projection. grid (4 nTiles, 40 mTiles), 512 thr.
//   by < 8 : v tile (emits vw = v_*wa and vT)   by >= 8 : q tile
// ============================================================
__global__ __launch_bounds__(512) void proj_k(
    const float* __restrict__ v, const float* __restrict__ q,
    const float* __restrict__ bv, const float* __restrict__ bq,
    const float* __restrict__ wa)
{
    extern __shared__ __align__(16) char smem[];
    __half* As = (__half*)smem;                 // [128][136]
    __half* Bs = (__half*)(smem + 128*PR_S*2);  // [128][136] (W^T tile, k-minor)

    int t = threadIdx.x;
    int by = blockIdx.y;
    bool isV = by < 8;
    int my = isV ? by : (by - 8);
    int bn = blockIdx.x * 128;
    int bm = my * 128;

    const float* A    = isV ? v  : q;
    const float* bias = isV ? bv : bq;
    const __half* WT  = isV ? g_WvT : g_WqT;

    // load A fp32 -> f16 smem [m][k]
    #pragma unroll
    for (int it = 0; it < 8; it++) {
        int fi = t + it*512;                 // 4096 float4
        int m = fi >> 5, k = (fi & 31)*4;
        float4 f = *(const float4*)(A + (size_t)(bm+m)*DIN + k);
        __half2 h0 = __floats2half2_rn(f.x, f.y);
        __half2 h1 = __floats2half2_rn(f.z, f.w);
        uint2 u; u.x = *(uint32_t*)&h0; u.y = *(uint32_t*)&h1;
        *(uint2*)(As + m*PR_S + k) = u;
    }
    // load WT f16 [n][k] via float4 (conflict-free)
    #pragma unroll
    for (int it = 0; it < 4; it++) {
        int fi = t + it*512;                 // 2048 float4
        int n = fi >> 4, k = (fi & 15)*8;
        *(float4*)(Bs + n*PR_S + k) = *(const float4*)(WT + (size_t)(bn+n)*DIN + k);
    }
    __syncthreads();

    int lane = t & 31, wid = t >> 5;
    int warpM = wid >> 2, warpN = wid & 3;   // 4x4 warps, 32x32 warp tile
    int lr = lane >> 2, lc = (lane & 3)*2;

    float acc[2][4][4] = {};
    #pragma unroll
    for (int ks = 0; ks < 8; ks++) {
        int k0 = ks*16;
        uint32_t a[2][4], b[4][2];
        #pragma unroll
        for (int mt = 0; mt < 2; mt++) {
            const __half* ab = As + (warpM*32 + mt*16 + lr)*PR_S + k0 + lc;
            a[mt][0] = *(const uint32_t*)ab;
            a[mt][1] = *(const uint32_t*)(ab + 8*PR_S);
            a[mt][2] = *(const uint32_t*)(ab + 8);
            a[mt][3] = *(const uint32_t*)(ab + 8*PR_S + 8);
        }
        #pragma unroll
        for (int nt = 0; nt < 4; nt++) {
            const __half* bb = Bs + (warpN*32 + nt*8 + lr)*PR_S + k0 + lc;
            b[nt][0] = *(const uint32_t*)bb;
            b[nt][1] = *(const uint32_t*)(bb + 8);
        }
        #pragma unroll
        for (int mt = 0; mt < 2; mt++)
            #pragma unroll
            for (int nt = 0; nt < 4; nt++)
                mma16816(acc[mt][nt], a[mt], b[nt]);
    }

    if (isV) __syncthreads();   // As reused as transpose staging

    #pragma unroll
    for (int mt = 0; mt < 2; mt++) {
        int rowL = warpM*32 + mt*16 + lr;
        #pragma unroll
        for (int nt = 0; nt < 4; nt++) {
            int colL = warpN*32 + nt*8 + lc;
            int col = bn + colL;
            float b0 = bias[col], b1 = bias[col+1];
            float v00 = acc[mt][nt][0] + b0, v01 = acc[mt][nt][1] + b1;
            float v10 = acc[mt][nt][2] + b0, v11 = acc[mt][nt][3] + b1;
            int row = bm + rowL;
            if (!isV) {
                *(__half2*)(g_q16 + (size_t)row*DPROJ + col) =
                    __floats2half2_rn(v00, v01);
                *(__half2*)(g_q16 + (size_t)(row+8)*DPROJ + col) =
                    __floats2half2_rn(v10, v11);
            } else {
                float w0 = wa[col & 255], w1 = wa[(col+1) & 255];
                *(__half2*)(g_vw16 + (size_t)row*DPROJ + col) =
                    __floats2half2_rn(v00*w0, v01*w1);
                *(__half2*)(g_vw16 + (size_t)(row+8)*DPROJ + col) =
                    __floats2half2_rn(v10*w0, v11*w1);
                __half* tr = As;   // tr[n][m]
                tr[colL*PR_S + rowL]       = __float2half(v00);
                tr[(colL+1)*PR_S + rowL]   = __float2half(v01);
                tr[colL*PR_S + rowL+8]     = __float2half(v10);
                tr[(colL+1)*PR_S + rowL+8] = __float2half(v11);
            }
        }
    }

    if (isV) {
        __syncthreads();
        const __half* tr = As;
        int b = my;   // one M tile == one batch for v
        #pragma unroll
        for (int it = 0; it < 4; it++) {
            int fi = t + it*512;             // 2048 float4
            int n = fi >> 4, k = (fi & 15)*8;
            *(float4*)(g_vT16 + ((size_t)b*DPROJ + bn + n)*NV_ + k) =
                *(const float4*)(tr + n*PR_S + k);
        }
    }
}

// ============================================================
// Score kernel: per (jt, h, b). 512 threads.
//  P1: S[128i,64j] = vw @ q^T (mma) -> softmax over i -> att write
//  P2: T[64j,256d] = e @ vT^T (mma) -> head atomics weighted by inv*q
// ============================================================
__global__ __launch_bounds__(512) void score_k(float* __restrict__ att_out)
{
    extern __shared__ __align__(16) char smem[];
    __half* vws = (__half*)smem;                  // P1 vw [128][264]; P2 vT [256][136]
    __half* qs  = (__half*)(smem + 69632);        // [64][264]
    float*  sc  = (float*) (smem + 103424);       // [64][132]
    __half* ebf = (__half*)(smem + 137216);       // [64][136]
    float*  inv = (float*) (smem + 154624);       // [64]

    int t = threadIdx.x;
    int jt = blockIdx.x, h = blockIdx.y, b = blockIdx.z;
    int lane = t & 31, wid = t >> 5;
    int lr = lane >> 2, lc = (lane & 3)*2;

    const __half* vwg = g_vw16 + ((size_t)b*NV_)*DPROJ + h*HD;
    const __half* qg  = g_q16  + ((size_t)(b*NQ_ + jt*64))*DPROJ + h*HD;

    #pragma unroll
    for (int it = 0; it < 8; it++) {
        int fi = t + it*512;                 // 4096 float4 : vw 128x256
        int i = fi >> 5, k = (fi & 31)*8;
        *(float4*)(vws + i*VW_S + k) = *(const float4*)(vwg + (size_t)i*DPROJ + k);
    }
    #pragma unroll
    for (int it = 0; it < 4; it++) {
        int fi = t + it*512;                 // 2048 float4 : q 64x256
        int j = fi >> 5, k = (fi & 31)*8;
        *(float4*)(qs + j*VW_S + k) = *(const float4*)(qg + (size_t)j*DPROJ + k);
    }
    __syncthreads();

    // -------- phase 1: warps 4(i) x 4(j), warp tile 32x16 --------
    {
        int iw = (wid >> 2)*32, jw = (wid & 3)*16;
        float acc[2][2][4] = {};
        #pragma unroll
        for (int ks = 0; ks < 16; ks++) {
            int k0 = ks*16;
            uint32_t a[2][4], bq[2][2];
            #pragma unroll
            for (int mi = 0; mi < 2; mi++) {
                const __half* ab = vws + (iw + mi*16 + lr)*VW_S + k0 + lc;
                a[mi][0] = *(const uint32_t*)ab;
                a[mi][1] = *(const uint32_t*)(ab + 8*VW_S);
                a[mi][2] = *(const uint32_t*)(ab + 8);
                a[mi][3] = *(const uint32_t*)(ab + 8*VW_S + 8);
            }
            #pragma unroll
            for (int nj = 0; nj < 2; nj++) {
                const __half* bb = qs + (jw + nj*8 + lr)*VW_S + k0 + lc;
                bq[nj][0] = *(const uint32_t*)bb;
                bq[nj][1] = *(const uint32_t*)(bb + 8);
            }
            #pragma unroll
            for (int mi = 0; mi < 2; mi++)
                #pragma unroll
                for (int nj = 0; nj < 2; nj++)
                    mma16816(acc[mi][nj], a[mi], bq[nj]);
        }
        #pragma unroll
        for (int mi = 0; mi < 2; mi++) {
            int i0 = iw + mi*16 + lr;
            #pragma unroll
            for (int nj = 0; nj < 2; nj++) {
                int j0 = jw + nj*8 + lc;
                sc[j0*SC_S + i0]       = acc[mi][nj][0];
                sc[(j0+1)*SC_S + i0]   = acc[mi][nj][1];
                sc[j0*SC_S + i0+8]     = acc[mi][nj][2];
                sc[(j0+1)*SC_S + i0+8] = acc[mi][nj][3];
            }
        }
    }
    __syncthreads();

    // -------- softmax over i : 16 warps x 4 cols --------
    #pragma unroll
    for (int rr = 0; rr < 4; rr++) {
        int j = wid*4 + rr;
        float4 x = *(float4*)(sc + j*SC_S + lane*4);
        float mx = fmaxf(fmaxf(x.x, x.y), fmaxf(x.z, x.w));
        #pragma unroll
        for (int off = 16; off; off >>= 1)
            mx = fmaxf(mx, __shfl_xor_sync(0xffffffffu, mx, off));
        float4 e;
        e.x = __expf(x.x - mx); e.y = __expf(x.y - mx);
        e.z = __expf(x.z - mx); e.w = __expf(x.w - mx);
        float s = e.x + e.y + e.z + e.w;
        #pragma unroll
        for (int off = 16; off; off >>= 1)
            s += __shfl_xor_sync(0xffffffffu, s, off);
        *(float4*)(sc + j*SC_S + lane*4) = e;
        *(__half2*)(ebf + j*EB_S + lane*4)     = __floats2half2_rn(e.x, e.y);
        *(__half2*)(ebf + j*EB_S + lane*4 + 2) = __floats2half2_rn(e.z, e.w);
        if (lane == 0) inv[j] = 1.0f / s;
    }
    __syncthreads();

    // -------- load vT (overwrites vws) + write att --------
    const __half* vtg = g_vT16 + ((size_t)b*DPROJ + h*HD)*NV_;
    #pragma unroll
    for (int it = 0; it < 8; it++) {
        int fi = t + it*512;                 // 4096 float4 : vT 256x128
        int d = fi >> 4, k = (fi & 15)*8;
        *(float4*)(vws + d*VT_S + k) = *(const float4*)(vtg + (size_t)d*NV_ + k);
    }
    float* attp = att_out + ((size_t)(b*2 + h)*NV_)*NQ_ + jt*64;
    #pragma unroll
    for (int it = 0; it < 16; it++) {
        int e = it*512 + t;
        int i = e >> 6, j = e & 63;
        attp[(size_t)i*NQ_ + j] = sc[j*SC_S + i] * inv[j];
    }
    __syncthreads();

    // -------- phase 2: warps 2(j) x 8(d), warp tile 32x32 --------
    {
        int jw2 = (wid >> 3)*32, dw = (wid & 7)*32;
        float acc[2][4][4] = {};
        #pragma unroll
        for (int ks = 0; ks < 8; ks++) {
            int k0 = ks*16;
            uint32_t a[2][4], bv[4][2];
            #pragma unroll
            for (int mi = 0; mi < 2; mi++) {
                const __half* ab = ebf + (jw2 + mi*16 + lr)*EB_S + k0 + lc;
                a[mi][0] = *(const uint32_t*)ab;
                a[mi][1] = *(const uint32_t*)(ab + 8*EB_S);
                a[mi][2] = *(const uint32_t*)(ab + 8);
                a[mi][3] = *(const uint32_t*)(ab + 8*EB_S + 8);
            }
            #pragma unroll
            for (int nt = 0; nt < 4; nt++) {
                const __half* bb = vws + (dw + nt*8 + lr)*VT_S + k0 + lc;
                bv[nt][0] = *(const uint32_t*)bb;
                bv[nt][1] = *(const uint32_t*)(bb + 8);
            }
            #pragma unroll
            for (int mi = 0; mi < 2; mi++)
                #pragma unroll
                for (int nt = 0; nt < 4; nt++)
                    mma16816(acc[mi][nt], a[mi], bv[nt]);
        }
        float* headp = g_head + (b*2 + h)*HD;
        #pragma unroll
        for (int nt = 0; nt < 4; nt++) {
            int d0 = dw + nt*8 + lc;
            float va = 0.f, vb = 0.f;
            #pragma unroll
            for (int mi = 0; mi < 2; mi++) {
                int j0 = jw2 + mi*16 + lr, j1 = j0 + 8;
                float w0 = inv[j0], w1 = inv[j1];
                float q00 = __half2float(qs[j0*VW_S + d0]);
                float q01 = __half2float(qs[j0*VW_S + d0+1]);
                float q10 = __half2float(qs[j1*VW_S + d0]);
                float q11 = __half2float(qs[j1*VW_S + d0+1]);
                va += acc[mi][nt][0]*w0*q00 + acc[mi][nt][2]*w1*q10;
                vb += acc[mi][nt][1]*w0*q01 + acc[mi][nt][3]*w1*q11;
            }
            va += __shfl_xor_sync(0xffffffffu, va, 4);
            va += __shfl_xor_sync(0xffffffffu, va, 8);
            va += __shfl_xor_sync(0xffffffffu, va, 16);
            vb += __shfl_xor_sync(0xffffffffu, vb, 4);
            vb += __shfl_xor_sync(0xffffffffu, vb, 8);
            vb += __shfl_xor_sync(0xffffffffu, vb, 16);
            if (lr == 0) {
                atomicAdd(headp + d0,     va);
                atomicAdd(headp + d0 + 1, vb);
            }
        }
    }
}

// ============================================================
// fused = head(8x512) @ Wo(512x256) + bo.
// 8 CTAs x 512 thr. Wo read ONCE: warp w owns K-slice [w*32, w*32+32),
// lane owns column blockIdx.x*32+lane. head in smem, reused for all 8 b.
// Cross-warp reduction in smem.
// ============================================================
__global__ __launch_bounds__(512) void fused_k(
    const float* __restrict__ Wo, const float* __restrict__ bo,
    float* __restrict__ out)
{
    __shared__ __align__(16) float hs[B_*DPROJ];   // 16 KB
    __shared__ float red[16][8][32];               // 16 KB
    int t = threadIdx.x, lane = t & 31, w = t >> 5;
    int col = blockIdx.x*32 + lane;

    #pragma unroll
    for (int it = 0; it < 2; it++) {
        int fi = t + it*512;                 // 1024 float4
        *(float4*)(hs + fi*4) = *(const float4*)(g_head + fi*4);
    }
    __syncthreads();

    float acc[8] = {};
    int k0 = w*32;
    #pragma unroll
    for (int k = 0; k < 32; k++) {
        float wv = Wo[(size_t)(k0 + k)*HD + col];
        #pragma unroll
        for (int b = 0; b < 8; b++)
            acc[b] += wv * hs[b*DPROJ + k0 + k];
    }
    #pragma unroll
    for (int b = 0; b < 8; b++) red[w][b][lane] = acc[b];
    __syncthreads();

    if (w < 8) {
        float s = 0.f;
        #pragma unroll
        for (int ww = 0; ww < 16; ww++) s += red[ww][w][lane];
        out[w*HD + col] = s + bo[col];
    }
}

// ============================================================
extern "C" void kernel_launch(void* const* d_in, const int* in_sizes, int n_in,
                              void* d_out, int out_size)
{
    const float* v  = (const float*)d_in[0];
    const float* q  = (const float*)d_in[1];
    const float* Wv = (const float*)d_in[2];
    const float* bv = (const float*)d_in[3];
    const float* Wq = (const float*)d_in[4];
    const float* bq = (const float*)d_in[5];
    const float* wa = (const float*)d_in[6];
    // d_in[7] = ba : constant shift before softmax -> drops out
    const float* Wo = (const float*)d_in[8];
    const float* bo = (const float*)d_in[9];
    float* out = (float*)d_out;

    const int PSM = 2 * 128 * PR_S * 2;   // 69632 B
    const int SSM = 154880;               // score smem
    cudaFuncSetAttribute(proj_k,  cudaFuncAttributeMaxDynamicSharedMemorySize, PSM);
    cudaFuncSetAttribute(score_k, cudaFuncAttributeMaxDynamicSharedMemorySize, SSM);

    transposeW_k<<<dim3(8, 2), 256>>>(Wv, Wq);
    proj_k<<<dim3(4, 40), 512, PSM>>>(v, q, bv, bq, wa);
    score_k<<<dim3(8, 2, 8), 512, SSM>>>(out + B_*HD);
    fused_k<<<8, 512>>>(Wo, bo, out);
}

// round 6
// speedup vs baseline: 1.3084x; 1.0572x over previous
#include <cuda_runtime.h>
#include <cuda_fp16.h>
#include <stdint.h>

#define B_    8
#define NV_   128
#define NQ_   512
#define DIN   128
#define DPROJ 512
#define HD    256

// smem strides (element units): row step = 4 banks -> conflict-free frag loads
#define PR_S  136   // proj tiles [x][136] f16
#define VW_S  264   // score vw/q tiles [x][264] f16 (K=256)
#define SC_S  132   // score matrix [j][132] fp32 (i=128)
#define EB_S  136   // exp tile [j][136] f16
#define VT_S  136   // vT tile [d][136] f16

// ---- device scratch (allocations forbidden) ----
__device__ __half g_q16 [B_*NQ_*DPROJ];   // q_  : [b*512+j][512]
__device__ __half g_vw16[B_*NV_*DPROJ];   // v_*wa : [b*128+i][512]
__device__ __half g_vT16[B_*DPROJ*NV_];   // v_^T : [b][512][128]
__device__ __half g_WvT [DPROJ*DIN];      // Wv^T f16 [512][128]
__device__ __half g_WqT [DPROJ*DIN];      // Wq^T f16 [512][128]
__device__ float  g_head[B_*DPROJ];

__device__ __forceinline__ void mma16816(float* c, const uint32_t* a, const uint32_t* b) {
    asm volatile(
        "mma.sync.aligned.m16n8k16.row.col.f32.f16.f16.f32 "
        "{%0,%1,%2,%3}, {%4,%5,%6,%7}, {%8,%9}, {%0,%1,%2,%3};\n"
        : "+f"(c[0]), "+f"(c[1]), "+f"(c[2]), "+f"(c[3])
        : "r"(a[0]), "r"(a[1]), "r"(a[2]), "r"(a[3]), "r"(b[0]), "r"(b[1]));
}

// ============================================================
// Tiled W transpose: W[128][512] fp32 -> WT[512][128] f16, via smem.
// grid (8 ntiles, 2 which), 256 thr. Coalesced read AND write.
// CTA (0,0) zeroes g_head; CTA (0,1) zeroes out fused region.
// ============================================================
__global__ __launch_bounds__(256) void transposeW_k(
    const float* __restrict__ Wv, const float* __restrict__ Wq,
    float* __restrict__ out)
{
    __shared__ __align__(16) __half s[64*136];   // [nn][k], stride 136
    const float* W = blockIdx.y ? Wq : Wv;
    __half* WT = blockIdx.y ? g_WqT : g_WvT;
    int t = threadIdx.x;
    int n0 = blockIdx.x * 64;

    if (blockIdx.x == 0) {
        if (blockIdx.y == 0) {
            #pragma unroll
            for (int it = 0; it < 16; it++) g_head[t + it*256] = 0.f;
        } else {
            #pragma unroll
            for (int it = 0; it < 8; it++) out[t + it*256] = 0.f;  // 2048 fused elems
        }
    }

    #pragma unroll
    for (int it = 0; it < 32; it++) {
        int fi = t + it*256;                 // 8192 elements
        int k = fi >> 6, nn = fi & 63;
        s[nn*136 + k] = __float2half(W[(size_t)k*DPROJ + n0 + nn]);
    }
    __syncthreads();
    #pragma unroll
    for (int it = 0; it < 4; it++) {
        int fi = t + it*256;                 // 1024 float4
        int n = fi >> 4, kq = (fi & 15)*8;
        *(float4*)(WT + (size_t)(n0 + n)*DIN + kq) =
            *(const float4*)(s + n*136 + kq);
    }
}

// ============================================================
// Combined projection. grid (4 nTiles, 40 mTiles), 512 thr.
//   by < 8 : v tile (emits vw = v_*wa and vT)   by >= 8 : q tile
// ============================================================
__global__ __launch_bounds__(512) void proj_k(
    const float* __restrict__ v, const float* __restrict__ q,
    const float* __restrict__ bv, const float* __restrict__ bq,
    const float* __restrict__ wa)
{
    extern __shared__ __align__(16) char smem[];
    __half* As = (__half*)smem;                 // [128][136]
    __half* Bs = (__half*)(smem + 128*PR_S*2);  // [128][136] (W^T tile, k-minor)

    int t = threadIdx.x;
    int by = blockIdx.y;
    bool isV = by < 8;
    int my = isV ? by : (by - 8);
    int bn = blockIdx.x * 128;
    int bm = my * 128;

    const float* A    = isV ? v  : q;
    const float* bias = isV ? bv : bq;
    const __half* WT  = isV ? g_WvT : g_WqT;

    // load A fp32 -> f16 smem [m][k]
    #pragma unroll
    for (int it = 0; it < 8; it++) {
        int fi = t + it*512;                 // 4096 float4
        int m = fi >> 5, k = (fi & 31)*4;
        float4 f = *(const float4*)(A + (size_t)(bm+m)*DIN + k);
        __half2 h0 = __floats2half2_rn(f.x, f.y);
        __half2 h1 = __floats2half2_rn(f.z, f.w);
        uint2 u; u.x = *(uint32_t*)&h0; u.y = *(uint32_t*)&h1;
        *(uint2*)(As + m*PR_S + k) = u;
    }
    // load WT f16 [n][k] via float4 (conflict-free)
    #pragma unroll
    for (int it = 0; it < 4; it++) {
        int fi = t + it*512;                 // 2048 float4
        int n = fi >> 4, k = (fi & 15)*8;
        *(float4*)(Bs + n*PR_S + k) = *(const float4*)(WT + (size_t)(bn+n)*DIN + k);
    }
    __syncthreads();

    int lane = t & 31, wid = t >> 5;
    int warpM = wid >> 2, warpN = wid & 3;   // 4x4 warps, 32x32 warp tile
    int lr = lane >> 2, lc = (lane & 3)*2;

    float acc[2][4][4] = {};
    #pragma unroll
    for (int ks = 0; ks < 8; ks++) {
        int k0 = ks*16;
        uint32_t a[2][4], b[4][2];
        #pragma unroll
        for (int mt = 0; mt < 2; mt++) {
            const __half* ab = As + (warpM*32 + mt*16 + lr)*PR_S + k0 + lc;
            a[mt][0] = *(const uint32_t*)ab;
            a[mt][1] = *(const uint32_t*)(ab + 8*PR_S);
            a[mt][2] = *(const uint32_t*)(ab + 8);
            a[mt][3] = *(const uint32_t*)(ab + 8*PR_S + 8);
        }
        #pragma unroll
        for (int nt = 0; nt < 4; nt++) {
            const __half* bb = Bs + (warpN*32 + nt*8 + lr)*PR_S + k0 + lc;
            b[nt][0] = *(const uint32_t*)bb;
            b[nt][1] = *(const uint32_t*)(bb + 8);
        }
        #pragma unroll
        for (int mt = 0; mt < 2; mt++)
            #pragma unroll
            for (int nt = 0; nt < 4; nt++)
                mma16816(acc[mt][nt], a[mt], b[nt]);
    }

    if (isV) __syncthreads();   // As reused as transpose staging

    #pragma unroll
    for (int mt = 0; mt < 2; mt++) {
        int rowL = warpM*32 + mt*16 + lr;
        #pragma unroll
        for (int nt = 0; nt < 4; nt++) {
            int colL = warpN*32 + nt*8 + lc;
            int col = bn + colL;
            float b0 = bias[col], b1 = bias[col+1];
            float v00 = acc[mt][nt][0] + b0, v01 = acc[mt][nt][1] + b1;
            float v10 = acc[mt][nt][2] + b0, v11 = acc[mt][nt][3] + b1;
            int row = bm + rowL;
            if (!isV) {
                *(__half2*)(g_q16 + (size_t)row*DPROJ + col) =
                    __floats2half2_rn(v00, v01);
                *(__half2*)(g_q16 + (size_t)(row+8)*DPROJ + col) =
                    __floats2half2_rn(v10, v11);
            } else {
                float w0 = wa[col & 255], w1 = wa[(col+1) & 255];
                *(__half2*)(g_vw16 + (size_t)row*DPROJ + col) =
                    __floats2half2_rn(v00*w0, v01*w1);
                *(__half2*)(g_vw16 + (size_t)(row+8)*DPROJ + col) =
                    __floats2half2_rn(v10*w0, v11*w1);
                __half* tr = As;   // tr[n][m]
                tr[colL*PR_S + rowL]       = __float2half(v00);
                tr[(colL+1)*PR_S + rowL]   = __float2half(v01);
                tr[colL*PR_S + rowL+8]     = __float2half(v10);
                tr[(colL+1)*PR_S + rowL+8] = __float2half(v11);
            }
        }
    }

    if (isV) {
        __syncthreads();
        const __half* tr = As;
        int b = my;   // one M tile == one batch for v
        #pragma unroll
        for (int it = 0; it < 4; it++) {
            int fi = t + it*512;             // 2048 float4
            int n = fi >> 4, k = (fi & 15)*8;
            *(float4*)(g_vT16 + ((size_t)b*DPROJ + bn + n)*NV_ + k) =
                *(const float4*)(tr + n*PR_S + k);
        }
    }
}

// ============================================================
// Score kernel: per (jt, h, b). 512 threads.
//  P1: S[128i,64j] = vw @ q^T (mma) -> softmax over i -> att write
//  P2: T[64j,256d] = e @ vT^T (mma) -> head atomics weighted by inv*q
// ============================================================
__global__ __launch_bounds__(512) void score_k(float* __restrict__ att_out)
{
    extern __shared__ __align__(16) char smem[];
    __half* vws = (__half*)smem;                  // P1 vw [128][264]; P2 vT [256][136]
    __half* qs  = (__half*)(smem + 69632);        // [64][264]
    float*  sc  = (float*) (smem + 103424);       // [64][132]
    __half* ebf = (__half*)(smem + 137216);       // [64][136]
    float*  inv = (float*) (smem + 154624);       // [64]

    int t = threadIdx.x;
    int jt = blockIdx.x, h = blockIdx.y, b = blockIdx.z;
    int lane = t & 31, wid = t >> 5;
    int lr = lane >> 2, lc = (lane & 3)*2;

    const __half* vwg = g_vw16 + ((size_t)b*NV_)*DPROJ + h*HD;
    const __half* qg  = g_q16  + ((size_t)(b*NQ_ + jt*64))*DPROJ + h*HD;

    #pragma unroll
    for (int it = 0; it < 8; it++) {
        int fi = t + it*512;                 // 4096 float4 : vw 128x256
        int i = fi >> 5, k = (fi & 31)*8;
        *(float4*)(vws + i*VW_S + k) = *(const float4*)(vwg + (size_t)i*DPROJ + k);
    }
    #pragma unroll
    for (int it = 0; it < 4; it++) {
        int fi = t + it*512;                 // 2048 float4 : q 64x256
        int j = fi >> 5, k = (fi & 31)*8;
        *(float4*)(qs + j*VW_S + k) = *(const float4*)(qg + (size_t)j*DPROJ + k);
    }
    __syncthreads();

    // -------- phase 1: warps 4(i) x 4(j), warp tile 32x16 --------
    {
        int iw = (wid >> 2)*32, jw = (wid & 3)*16;
        float acc[2][2][4] = {};
        #pragma unroll
        for (int ks = 0; ks < 16; ks++) {
            int k0 = ks*16;
            uint32_t a[2][4], bq[2][2];
            #pragma unroll
            for (int mi = 0; mi < 2; mi++) {
                const __half* ab = vws + (iw + mi*16 + lr)*VW_S + k0 + lc;
                a[mi][0] = *(const uint32_t*)ab;
                a[mi][1] = *(const uint32_t*)(ab + 8*VW_S);
                a[mi][2] = *(const uint32_t*)(ab + 8);
                a[mi][3] = *(const uint32_t*)(ab + 8*VW_S + 8);
            }
            #pragma unroll
            for (int nj = 0; nj < 2; nj++) {
                const __half* bb = qs + (jw + nj*8 + lr)*VW_S + k0 + lc;
                bq[nj][0] = *(const uint32_t*)bb;
                bq[nj][1] = *(const uint32_t*)(bb + 8);
            }
            #pragma unroll
            for (int mi = 0; mi < 2; mi++)
                #pragma unroll
                for (int nj = 0; nj < 2; nj++)
                    mma16816(acc[mi][nj], a[mi], bq[nj]);
        }
        #pragma unroll
        for (int mi = 0; mi < 2; mi++) {
            int i0 = iw + mi*16 + lr;
            #pragma unroll
            for (int nj = 0; nj < 2; nj++) {
                int j0 = jw + nj*8 + lc;
                sc[j0*SC_S + i0]       = acc[mi][nj][0];
                sc[(j0+1)*SC_S + i0]   = acc[mi][nj][1];
                sc[j0*SC_S + i0+8]     = acc[mi][nj][2];
                sc[(j0+1)*SC_S + i0+8] = acc[mi][nj][3];
            }
        }
    }
    __syncthreads();

    // -------- softmax over i : 16 warps x 4 cols --------
    #pragma unroll
    for (int rr = 0; rr < 4; rr++) {
        int j = wid*4 + rr;
        float4 x = *(float4*)(sc + j*SC_S + lane*4);
        float mx = fmaxf(fmaxf(x.x, x.y), fmaxf(x.z, x.w));
        #pragma unroll
        for (int off = 16; off; off >>= 1)
            mx = fmaxf(mx, __shfl_xor_sync(0xffffffffu, mx, off));
        float4 e;
        e.x = __expf(x.x - mx); e.y = __expf(x.y - mx);
        e.z = __expf(x.z - mx); e.w = __expf(x.w - mx);
        float s = e.x + e.y + e.z + e.w;
        #pragma unroll
        for (int off = 16; off; off >>= 1)
            s += __shfl_xor_sync(0xffffffffu, s, off);
        *(float4*)(sc + j*SC_S + lane*4) = e;
        *(__half2*)(ebf + j*EB_S + lane*4)     = __floats2half2_rn(e.x, e.y);
        *(__half2*)(ebf + j*EB_S + lane*4 + 2) = __floats2half2_rn(e.z, e.w);
        if (lane == 0) inv[j] = 1.0f / s;
    }
    __syncthreads();

    // -------- load vT (overwrites vws) + write att --------
    const __half* vtg = g_vT16 + ((size_t)b*DPROJ + h*HD)*NV_;
    #pragma unroll
    for (int it = 0; it < 8; it++) {
        int fi = t + it*512;                 // 4096 float4 : vT 256x128
        int d = fi >> 4, k = (fi & 15)*8;
        *(float4*)(vws + d*VT_S + k) = *(const float4*)(vtg + (size_t)d*NV_ + k);
    }
    float* attp = att_out + ((size_t)(b*2 + h)*NV_)*NQ_ + jt*64;
    #pragma unroll
    for (int it = 0; it < 16; it++) {
        int e = it*512 + t;
        int i = e >> 6, j = e & 63;
        attp[(size_t)i*NQ_ + j] = sc[j*SC_S + i] * inv[j];
    }
    __syncthreads();

    // -------- phase 2: warps 2(j) x 8(d), warp tile 32x32 --------
    {
        int jw2 = (wid >> 3)*32, dw = (wid & 7)*32;
        float acc[2][4][4] = {};
        #pragma unroll
        for (int ks = 0; ks < 8; ks++) {
            int k0 = ks*16;
            uint32_t a[2][4], bv[4][2];
            #pragma unroll
            for (int mi = 0; mi < 2; mi++) {
                const __half* ab = ebf + (jw2 + mi*16 + lr)*EB_S + k0 + lc;
                a[mi][0] = *(const uint32_t*)ab;
                a[mi][1] = *(const uint32_t*)(ab + 8*EB_S);
                a[mi][2] = *(const uint32_t*)(ab + 8);
                a[mi][3] = *(const uint32_t*)(ab + 8*EB_S + 8);
            }
            #pragma unroll
            for (int nt = 0; nt < 4; nt++) {
                const __half* bb = vws + (dw + nt*8 + lr)*VT_S + k0 + lc;
                bv[nt][0] = *(const uint32_t*)bb;
                bv[nt][1] = *(const uint32_t*)(bb + 8);
            }
            #pragma unroll
            for (int mi = 0; mi < 2; mi++)
                #pragma unroll
                for (int nt = 0; nt < 4; nt++)
                    mma16816(acc[mi][nt], a[mi], bv[nt]);
        }
        float* headp = g_head + (b*2 + h)*HD;
        #pragma unroll
        for (int nt = 0; nt < 4; nt++) {
            int d0 = dw + nt*8 + lc;
            float va = 0.f, vb = 0.f;
            #pragma unroll
            for (int mi = 0; mi < 2; mi++) {
                int j0 = jw2 + mi*16 + lr, j1 = j0 + 8;
                float w0 = inv[j0], w1 = inv[j1];
                float q00 = __half2float(qs[j0*VW_S + d0]);
                float q01 = __half2float(qs[j0*VW_S + d0+1]);
                float q10 = __half2float(qs[j1*VW_S + d0]);
                float q11 = __half2float(qs[j1*VW_S + d0+1]);
                va += acc[mi][nt][0]*w0*q00 + acc[mi][nt][2]*w1*q10;
                vb += acc[mi][nt][1]*w0*q01 + acc[mi][nt][3]*w1*q11;
            }
            va += __shfl_xor_sync(0xffffffffu, va, 4);
            va += __shfl_xor_sync(0xffffffffu, va, 8);
            va += __shfl_xor_sync(0xffffffffu, va, 16);
            vb += __shfl_xor_sync(0xffffffffu, vb, 4);
            vb += __shfl_xor_sync(0xffffffffu, vb, 8);
            vb += __shfl_xor_sync(0xffffffffu, vb, 16);
            if (lr == 0) {
                atomicAdd(headp + d0,     va);
                atomicAdd(headp + d0 + 1, vb);
            }
        }
    }
}

// ============================================================
// fused = head(8x512) @ Wo(512x256) + bo.
// grid (8 colblocks, 4 kslices) x 512 thr; atomicAdd partials into out
// (out fused region zeroed by transposeW_k). Per CTA: 16KB of Wo,
// 8 LDG + 64 FMA per thread. Wo read exactly once chip-wide.
// ============================================================
__global__ __launch_bounds__(512) void fused_k(
    const float* __restrict__ Wo, const float* __restrict__ bo,
    float* __restrict__ out)
{
    __shared__ float hsl[8*128];        // head slice [b][128]
    __shared__ float red[16][8][32];
    int t = threadIdx.x, lane = t & 31, w = t >> 5;
    int cb = blockIdx.x, ks = blockIdx.y;
    int col = cb*32 + lane;

    if (t < 256) {                      // stage head slice (coalesced 128-float runs)
        int b = t >> 5, i = t & 31;
        #pragma unroll
        for (int r = 0; r < 4; r++)
            hsl[b*128 + i + r*32] = g_head[b*DPROJ + ks*128 + i + r*32];
    }
    __syncthreads();

    int k0 = w*8;
    float acc[8] = {};
    #pragma unroll
    for (int kk = 0; kk < 8; kk++) {
        float wv = Wo[(size_t)(ks*128 + k0 + kk)*HD + col];
        #pragma unroll
        for (int b = 0; b < 8; b++)
            acc[b] += wv * hsl[b*128 + k0 + kk];
    }
    #pragma unroll
    for (int b = 0; b < 8; b++) red[w][b][lane] = acc[b];
    __syncthreads();

    if (w < 8) {
        float s = 0.f;
        #pragma unroll
        for (int ww = 0; ww < 16; ww++) s += red[ww][w][lane];
        if (ks == 0) s += bo[col];      // bias added exactly once
        atomicAdd(&out[w*HD + col], s);
    }
}

// ============================================================
extern "C" void kernel_launch(void* const* d_in, const int* in_sizes, int n_in,
                              void* d_out, int out_size)
{
    const float* v  = (const float*)d_in[0];
    const float* q  = (const float*)d_in[1];
    const float* Wv = (const float*)d_in[2];
    const float* bv = (const float*)d_in[3];
    const float* Wq = (const float*)d_in[4];
    const float* bq = (const float*)d_in[5];
    const float* wa = (const float*)d_in[6];
    // d_in[7] = ba : constant shift before softmax -> drops out
    const float* Wo = (const float*)d_in[8];
    const float* bo = (const float*)d_in[9];
    float* out = (float*)d_out;

    const int PSM = 2 * 128 * PR_S * 2;   // 69632 B
    const int SSM = 154880;               // score smem
    cudaFuncSetAttribute(proj_k,  cudaFuncAttributeMaxDynamicSharedMemorySize, PSM);
    cudaFuncSetAttribute(score_k, cudaFuncAttributeMaxDynamicSharedMemorySize, SSM);

    transposeW_k<<<dim3(8, 2), 256>>>(Wv, Wq, out);
    proj_k<<<dim3(4, 40), 512, PSM>>>(v, q, bv, bq, wa);
    score_k<<<dim3(8, 2, 8), 512, SSM>>>(out + B_*HD);
    fused_k<<<dim3(8, 4), 512>>>(Wo, bo, out);
}

// round 7
// speedup vs baseline: 1.3099x; 1.0012x over previous
#include <cuda_runtime.h>
#include <cuda_fp16.h>
#include <stdint.h>

#define B_    8
#define NV_   128
#define NQ_   512
#define DIN   128
#define DPROJ 512
#define HD    256

// smem strides (element units): row step = 4 banks -> conflict-free frag loads
#define PR_S  136   // proj tiles [x][136] f16
#define VW_S  264   // score vw/q tiles [x][264] f16 (K=256)
#define SC_S  132   // score matrix [j][132] fp32 (i=128)
#define EB_S  136   // exp tile [j][136] f16
#define VT_S  136   // vT tile [d][136] f16

// ---- device scratch (allocations forbidden) ----
__device__ __half g_q16 [B_*NQ_*DPROJ];   // q_  : [b*512+j][512]
__device__ __half g_vw16[B_*NV_*DPROJ];   // v_*wa : [b*128+i][512]
__device__ __half g_vT16[B_*DPROJ*NV_];   // v_^T : [b][512][128]
__device__ __half g_WvT [DPROJ*DIN];      // Wv^T f16 [512][128]
__device__ __half g_WqT [DPROJ*DIN];      // Wq^T f16 [512][128]
__device__ float  g_head[B_*DPROJ];
__device__ float  g_dummy[32];            // prefetch checksum sink

__device__ __forceinline__ void mma16816(float* c, const uint32_t* a, const uint32_t* b) {
    asm volatile(
        "mma.sync.aligned.m16n8k16.row.col.f32.f16.f16.f32 "
        "{%0,%1,%2,%3}, {%4,%5,%6,%7}, {%8,%9}, {%0,%1,%2,%3};\n"
        : "+f"(c[0]), "+f"(c[1]), "+f"(c[2]), "+f"(c[3])
        : "r"(a[0]), "r"(a[1]), "r"(a[2]), "r"(a[3]), "r"(b[0]), "r"(b[1]));
}

// ============================================================
// Tiled W transpose: W[128][512] fp32 -> WT[512][128] f16, via smem.
// grid (8 ntiles, 2 which), 256 thr.
// Extras: zero g_head / out-fused region; PREFETCH Wo into L2
// (fused_k reads it last — L2 persists across launches).
// ============================================================
__global__ __launch_bounds__(256) void transposeW_k(
    const float* __restrict__ Wv, const float* __restrict__ Wq,
    const float* __restrict__ Wo, float* __restrict__ out)
{
    __shared__ __align__(16) __half s[64*136];   // [nn][k], stride 136
    const float* W = blockIdx.y ? Wq : Wv;
    __half* WT = blockIdx.y ? g_WqT : g_WvT;
    int t = threadIdx.x;
    int n0 = blockIdx.x * 64;

    if (blockIdx.x == 0) {
        if (blockIdx.y == 0) {
            #pragma unroll
            for (int it = 0; it < 16; it++) g_head[t + it*256] = 0.f;
        } else {
            #pragma unroll
            for (int it = 0; it < 8; it++) out[t + it*256] = 0.f;  // 2048 fused elems
        }
    }

    // ---- prefetch Wo (131072 floats = 32768 float4) into L2 ----
    {
        int gtid = (blockIdx.y*8 + blockIdx.x)*256 + t;    // 0..4095
        const float4* wo4 = (const float4*)Wo;
        float acc = 0.f;
        #pragma unroll
        for (int it = 0; it < 8; it++) {
            float4 f = wo4[gtid + it*4096];
            acc += f.x + f.y + f.z + f.w;
        }
        if (t == 0) g_dummy[blockIdx.y*8 + blockIdx.x] = acc;
    }

    #pragma unroll
    for (int it = 0; it < 32; it++) {
        int fi = t + it*256;                 // 8192 elements
        int k = fi >> 6, nn = fi & 63;
        s[nn*136 + k] = __float2half(W[(size_t)k*DPROJ + n0 + nn]);
    }
    __syncthreads();
    #pragma unroll
    for (int it = 0; it < 4; it++) {
        int fi = t + it*256;                 // 1024 float4
        int n = fi >> 4, kq = (fi & 15)*8;
        *(float4*)(WT + (size_t)(n0 + n)*DIN + kq) =
            *(const float4*)(s + n*136 + kq);
    }
}

// ============================================================
// Combined projection. grid (4 nTiles, 40 mTiles), 512 thr.
//   by < 8 : v tile (emits vw = v_*wa and vT)   by >= 8 : q tile
// ============================================================
__global__ __launch_bounds__(512) void proj_k(
    const float* __restrict__ v, const float* __restrict__ q,
    const float* __restrict__ bv, const float* __restrict__ bq,
    const float* __restrict__ wa)
{
    extern __shared__ __align__(16) char smem[];
    __half* As = (__half*)smem;                 // [128][136]
    __half* Bs = (__half*)(smem + 128*PR_S*2);  // [128][136] (W^T tile, k-minor)

    int t = threadIdx.x;
    int by = blockIdx.y;
    bool isV = by < 8;
    int my = isV ? by : (by - 8);
    int bn = blockIdx.x * 128;
    int bm = my * 128;

    const float* A    = isV ? v  : q;
    const float* bias = isV ? bv : bq;
    const __half* WT  = isV ? g_WvT : g_WqT;

    // load A fp32 -> f16 smem [m][k]
    #pragma unroll
    for (int it = 0; it < 8; it++) {
        int fi = t + it*512;                 // 4096 float4
        int m = fi >> 5, k = (fi & 31)*4;
        float4 f = *(const float4*)(A + (size_t)(bm+m)*DIN + k);
        __half2 h0 = __floats2half2_rn(f.x, f.y);
        __half2 h1 = __floats2half2_rn(f.z, f.w);
        uint2 u; u.x = *(uint32_t*)&h0; u.y = *(uint32_t*)&h1;
        *(uint2*)(As + m*PR_S + k) = u;
    }
    // load WT f16 [n][k] via float4 (conflict-free)
    #pragma unroll
    for (int it = 0; it < 4; it++) {
        int fi = t + it*512;                 // 2048 float4
        int n = fi >> 4, k = (fi & 15)*8;
        *(float4*)(Bs + n*PR_S + k) = *(const float4*)(WT + (size_t)(bn+n)*DIN + k);
    }
    __syncthreads();

    int lane = t & 31, wid = t >> 5;
    int warpM = wid >> 2, warpN = wid & 3;   // 4x4 warps, 32x32 warp tile
    int lr = lane >> 2, lc = (lane & 3)*2;

    float acc[2][4][4] = {};
    #pragma unroll
    for (int ks = 0; ks < 8; ks++) {
        int k0 = ks*16;
        uint32_t a[2][4], b[4][2];
        #pragma unroll
        for (int mt = 0; mt < 2; mt++) {
            const __half* ab = As + (warpM*32 + mt*16 + lr)*PR_S + k0 + lc;
            a[mt][0] = *(const uint32_t*)ab;
            a[mt][1] = *(const uint32_t*)(ab + 8*PR_S);
            a[mt][2] = *(const uint32_t*)(ab + 8);
            a[mt][3] = *(const uint32_t*)(ab + 8*PR_S + 8);
        }
        #pragma unroll
        for (int nt = 0; nt < 4; nt++) {
            const __half* bb = Bs + (warpN*32 + nt*8 + lr)*PR_S + k0 + lc;
            b[nt][0] = *(const uint32_t*)bb;
            b[nt][1] = *(const uint32_t*)(bb + 8);
        }
        #pragma unroll
        for (int mt = 0; mt < 2; mt++)
            #pragma unroll
            for (int nt = 0; nt < 4; nt++)
                mma16816(acc[mt][nt], a[mt], b[nt]);
    }

    if (isV) __syncthreads();   // As reused as transpose staging

    #pragma unroll
    for (int mt = 0; mt < 2; mt++) {
        int rowL = warpM*32 + mt*16 + lr;
        #pragma unroll
        for (int nt = 0; nt < 4; nt++) {
            int colL = warpN*32 + nt*8 + lc;
            int col = bn + colL;
            float b0 = bias[col], b1 = bias[col+1];
            float v00 = acc[mt][nt][0] + b0, v01 = acc[mt][nt][1] + b1;
            float v10 = acc[mt][nt][2] + b0, v11 = acc[mt][nt][3] + b1;
            int row = bm + rowL;
            if (!isV) {
                *(__half2*)(g_q16 + (size_t)row*DPROJ + col) =
                    __floats2half2_rn(v00, v01);
                *(__half2*)(g_q16 + (size_t)(row+8)*DPROJ + col) =
                    __floats2half2_rn(v10, v11);
            } else {
                float w0 = wa[col & 255], w1 = wa[(col+1) & 255];
                *(__half2*)(g_vw16 + (size_t)row*DPROJ + col) =
                    __floats2half2_rn(v00*w0, v01*w1);
                *(__half2*)(g_vw16 + (size_t)(row+8)*DPROJ + col) =
                    __floats2half2_rn(v10*w0, v11*w1);
                __half* tr = As;   // tr[n][m]
                tr[colL*PR_S + rowL]       = __float2half(v00);
                tr[(colL+1)*PR_S + rowL]   = __float2half(v01);
                tr[colL*PR_S + rowL+8]     = __float2half(v10);
                tr[(colL+1)*PR_S + rowL+8] = __float2half(v11);
            }
        }
    }

    if (isV) {
        __syncthreads();
        const __half* tr = As;
        int b = my;   // one M tile == one batch for v
        #pragma unroll
        for (int it = 0; it < 4; it++) {
            int fi = t + it*512;             // 2048 float4
            int n = fi >> 4, k = (fi & 15)*8;
            *(float4*)(g_vT16 + ((size_t)b*DPROJ + bn + n)*NV_ + k) =
                *(const float4*)(tr + n*PR_S + k);
        }
    }
}

// ============================================================
// Score kernel: per (jt, h, b). 512 threads.
//  P1: S[128i,64j] = vw @ q^T (mma) -> softmax over i -> att write
//  P2: T[64j,256d] = e @ vT^T (mma) -> head atomics weighted by inv*q
// ============================================================
__global__ __launch_bounds__(512) void score_k(float* __restrict__ att_out)
{
    extern __shared__ __align__(16) char smem[];
    __half* vws = (__half*)smem;                  // P1 vw [128][264]; P2 vT [256][136]
    __half* qs  = (__half*)(smem + 69632);        // [64][264]
    float*  sc  = (float*) (smem + 103424);       // [64][132]
    __half* ebf = (__half*)(smem + 137216);       // [64][136]
    float*  inv = (float*) (smem + 154624);       // [64]

    int t = threadIdx.x;
    int jt = blockIdx.x, h = blockIdx.y, b = blockIdx.z;
    int lane = t & 31, wid = t >> 5;
    int lr = lane >> 2, lc = (lane & 3)*2;

    const __half* vwg = g_vw16 + ((size_t)b*NV_)*DPROJ + h*HD;
    const __half* qg  = g_q16  + ((size_t)(b*NQ_ + jt*64))*DPROJ + h*HD;

    #pragma unroll
    for (int it = 0; it < 8; it++) {
        int fi = t + it*512;                 // 4096 float4 : vw 128x256
        int i = fi >> 5, k = (fi & 31)*8;
        *(float4*)(vws + i*VW_S + k) = *(const float4*)(vwg + (size_t)i*DPROJ + k);
    }
    #pragma unroll
    for (int it = 0; it < 4; it++) {
        int fi = t + it*512;                 // 2048 float4 : q 64x256
        int j = fi >> 5, k = (fi & 31)*8;
        *(float4*)(qs + j*VW_S + k) = *(const float4*)(qg + (size_t)j*DPROJ + k);
    }
    __syncthreads();

    // -------- phase 1: warps 4(i) x 4(j), warp tile 32x16 --------
    {
        int iw = (wid >> 2)*32, jw = (wid & 3)*16;
        float acc[2][2][4] = {};
        #pragma unroll
        for (int ks = 0; ks < 16; ks++) {
            int k0 = ks*16;
            uint32_t a[2][4], bq[2][2];
            #pragma unroll
            for (int mi = 0; mi < 2; mi++) {
                const __half* ab = vws + (iw + mi*16 + lr)*VW_S + k0 + lc;
                a[mi][0] = *(const uint32_t*)ab;
                a[mi][1] = *(const uint32_t*)(ab + 8*VW_S);
                a[mi][2] = *(const uint32_t*)(ab + 8);
                a[mi][3] = *(const uint32_t*)(ab + 8*VW_S + 8);
            }
            #pragma unroll
            for (int nj = 0; nj < 2; nj++) {
                const __half* bb = qs + (jw + nj*8 + lr)*VW_S + k0 + lc;
                bq[nj][0] = *(const uint32_t*)bb;
                bq[nj][1] = *(const uint32_t*)(bb + 8);
            }
            #pragma unroll
            for (int mi = 0; mi < 2; mi++)
                #pragma unroll
                for (int nj = 0; nj < 2; nj++)
                    mma16816(acc[mi][nj], a[mi], bq[nj]);
        }
        #pragma unroll
        for (int mi = 0; mi < 2; mi++) {
            int i0 = iw + mi*16 + lr;
            #pragma unroll
            for (int nj = 0; nj < 2; nj++) {
                int j0 = jw + nj*8 + lc;
                sc[j0*SC_S + i0]       = acc[mi][nj][0];
                sc[(j0+1)*SC_S + i0]   = acc[mi][nj][1];
                sc[j0*SC_S + i0+8]     = acc[mi][nj][2];
                sc[(j0+1)*SC_S + i0+8] = acc[mi][nj][3];
            }
        }
    }
    __syncthreads();

    // -------- softmax over i : 16 warps x 4 cols --------
    #pragma unroll
    for (int rr = 0; rr < 4; rr++) {
        int j = wid*4 + rr;
        float4 x = *(float4*)(sc + j*SC_S + lane*4);
        float mx = fmaxf(fmaxf(x.x, x.y), fmaxf(x.z, x.w));
        #pragma unroll
        for (int off = 16; off; off >>= 1)
            mx = fmaxf(mx, __shfl_xor_sync(0xffffffffu, mx, off));
        float4 e;
        e.x = __expf(x.x - mx); e.y = __expf(x.y - mx);
        e.z = __expf(x.z - mx); e.w = __expf(x.w - mx);
        float s = e.x + e.y + e.z + e.w;
        #pragma unroll
        for (int off = 16; off; off >>= 1)
            s += __shfl_xor_sync(0xffffffffu, s, off);
        *(float4*)(sc + j*SC_S + lane*4) = e;
        *(__half2*)(ebf + j*EB_S + lane*4)     = __floats2half2_rn(e.x, e.y);
        *(__half2*)(ebf + j*EB_S + lane*4 + 2) = __floats2half2_rn(e.z, e.w);
        if (lane == 0) inv[j] = 1.0f / s;
    }
    __syncthreads();

    // -------- load vT (overwrites vws) + write att --------
    const __half* vtg = g_vT16 + ((size_t)b*DPROJ + h*HD)*NV_;
    #pragma unroll
    for (int it = 0; it < 8; it++) {
        int fi = t + it*512;                 // 4096 float4 : vT 256x128
        int d = fi >> 4, k = (fi & 15)*8;
        *(float4*)(vws + d*VT_S + k) = *(const float4*)(vtg + (size_t)d*NV_ + k);
    }
    float* attp = att_out + ((size_t)(b*2 + h)*NV_)*NQ_ + jt*64;
    #pragma unroll
    for (int it = 0; it < 16; it++) {
        int e = it*512 + t;
        int i = e >> 6, j = e & 63;
        attp[(size_t)i*NQ_ + j] = sc[j*SC_S + i] * inv[j];
    }
    __syncthreads();

    // -------- phase 2: warps 2(j) x 8(d), warp tile 32x32 --------
    {
        int jw2 = (wid >> 3)*32, dw = (wid & 7)*32;
        float acc[2][4][4] = {};
        #pragma unroll
        for (int ks = 0; ks < 8; ks++) {
            int k0 = ks*16;
            uint32_t a[2][4], bv[4][2];
            #pragma unroll
            for (int mi = 0; mi < 2; mi++) {
                const __half* ab = ebf + (jw2 + mi*16 + lr)*EB_S + k0 + lc;
                a[mi][0] = *(const uint32_t*)ab;
                a[mi][1] = *(const uint32_t*)(ab + 8*EB_S);
                a[mi][2] = *(const uint32_t*)(ab + 8);
                a[mi][3] = *(const uint32_t*)(ab + 8*EB_S + 8);
            }
            #pragma unroll
            for (int nt = 0; nt < 4; nt++) {
                const __half* bb = vws + (dw + nt*8 + lr)*VT_S + k0 + lc;
                bv[nt][0] = *(const uint32_t*)bb;
                bv[nt][1] = *(const uint32_t*)(bb + 8);
            }
            #pragma unroll
            for (int mi = 0; mi < 2; mi++)
                #pragma unroll
                for (int nt = 0; nt < 4; nt++)
                    mma16816(acc[mi][nt], a[mi], bv[nt]);
        }
        float* headp = g_head + (b*2 + h)*HD;
        #pragma unroll
        for (int nt = 0; nt < 4; nt++) {
            int d0 = dw + nt*8 + lc;
            float va = 0.f, vb = 0.f;
            #pragma unroll
            for (int mi = 0; mi < 2; mi++) {
                int j0 = jw2 + mi*16 + lr, j1 = j0 + 8;
                float w0 = inv[j0], w1 = inv[j1];
                float q00 = __half2float(qs[j0*VW_S + d0]);
                float q01 = __half2float(qs[j0*VW_S + d0+1]);
                float q10 = __half2float(qs[j1*VW_S + d0]);
                float q11 = __half2float(qs[j1*VW_S + d0+1]);
                va += acc[mi][nt][0]*w0*q00 + acc[mi][nt][2]*w1*q10;
                vb += acc[mi][nt][1]*w0*q01 + acc[mi][nt][3]*w1*q11;
            }
            va += __shfl_xor_sync(0xffffffffu, va, 4);
            va += __shfl_xor_sync(0xffffffffu, va, 8);
            va += __shfl_xor_sync(0xffffffffu, va, 16);
            vb += __shfl_xor_sync(0xffffffffu, vb, 4);
            vb += __shfl_xor_sync(0xffffffffu, vb, 8);
            vb += __shfl_xor_sync(0xffffffffu, vb, 16);
            if (lr == 0) {
                atomicAdd(headp + d0,     va);
                atomicAdd(headp + d0 + 1, vb);
            }
        }
    }
}

// ============================================================
// fused = head(8x512) @ Wo(512x256) + bo.
// grid (8 colblocks, 16 kslices) x 512 thr; atomicAdd partials into out
// (zeroed by transposeW_k). Wo is L2-hot (prefetched). Per thread:
// 2 LDG + 16 FMA.
// ============================================================
__global__ __launch_bounds__(512) void fused_k(
    const float* __restrict__ Wo, const float* __restrict__ bo,
    float* __restrict__ out)
{
    __shared__ float hsl[8*32];         // head slice [b][32]
    __shared__ float red[16][8][32];
    int t = threadIdx.x, lane = t & 31, w = t >> 5;
    int cb = blockIdx.x, ks = blockIdx.y;
    int col = cb*32 + lane;

    if (t < 256) {                      // stage head slice
        int b = t >> 5, i = t & 31;
        hsl[b*32 + i] = g_head[b*DPROJ + ks*32 + i];
    }
    __syncthreads();

    float acc[8] = {};
    #pragma unroll
    for (int kk = 0; kk < 2; kk++) {
        int k = w*2 + kk;
        float wv = Wo[(size_t)(ks*32 + k)*HD + col];
        #pragma unroll
        for (int b = 0; b < 8; b++)
            acc[b] += wv * hsl[b*32 + k];
    }
    #pragma unroll
    for (int b = 0; b < 8; b++) red[w][b][lane] = acc[b];
    __syncthreads();

    if (w < 8) {
        float s = 0.f;
        #pragma unroll
        for (int ww = 0; ww < 16; ww++) s += red[ww][w][lane];
        if (ks == 0) s += bo[col];      // bias added exactly once
        atomicAdd(&out[w*HD + col], s);
    }
}

// ============================================================
extern "C" void kernel_launch(void* const* d_in, const int* in_sizes, int n_in,
                              void* d_out, int out_size)
{
    const float* v  = (const float*)d_in[0];
    const float* q  = (const float*)d_in[1];
    const float* Wv = (const float*)d_in[2];
    const float* bv = (const float*)d_in[3];
    const float* Wq = (const float*)d_in[4];
    const float* bq = (const float*)d_in[5];
    const float* wa = (const float*)d_in[6];
    // d_in[7] = ba : constant shift before softmax -> drops out
    const float* Wo = (const float*)d_in[8];
    const float* bo = (const float*)d_in[9];
    float* out = (float*)d_out;

    const int PSM = 2 * 128 * PR_S * 2;   // 69632 B
    const int SSM = 154880;               // score smem
    cudaFuncSetAttribute(proj_k,  cudaFuncAttributeMaxDynamicSharedMemorySize, PSM);
    cudaFuncSetAttribute(score_k, cudaFuncAttributeMaxDynamicSharedMemorySize, SSM);

    transposeW_k<<<dim3(8, 2), 256>>>(Wv, Wq, Wo, out);
    proj_k<<<dim3(4, 40), 512, PSM>>>(v, q, bv, bq, wa);
    score_k<<<dim3(8, 2, 8), 512, SSM>>>(out + B_*HD);
    fused_k<<<dim3(8, 16), 512>>>(Wo, bo, out);
}